// round 13
// baseline (speedup 1.0000x reference)
#include <cuda_runtime.h>
#include <cuda_fp16.h>
#include <cstdint>
#include <math.h>

#define N_NODES     500000
#define HIDDEN      256
#define NUM_CLASSES 104
#define AUX_DIM     2
#define NUM_GRAPHS  2048
#define D_IN        (NUM_CLASSES + AUX_DIM)   // 106
#define GRAPH_X     128
#define CP2         112                        // padded class dim (7 col-warps x 16)

// smem layout (units: halves)
#define WG_ST   520                            // Wg row stride (k), pad 8 -> conflict-free ldsm
#define WT_ST   264                            // Wt row stride
#define AS_ST   72                             // A row stride (64 + pad 8)
#define WG_OFF  0                              // 112*520 = 58240
#define WT_OFF  58240                          // 112*264 = 29568
#define A_OFF   87808
#define A_BUF   (128 * AS_ST)                  // 9216
#define DYN_BYTES ((A_OFF + 2 * A_BUF) * 2)    // 212480 bytes

// ---------------- device scratch ----------------
__device__ __half g_Wg_h[CP2 * 2 * HIDDEN];    // [112 n][512 k] fp16
__device__ __half g_Wt_h[CP2 * HIDDEN];        // [112 n][256 k] fp16
__device__ float  g_bg_pad[CP2];
__device__ float  g_bt_pad[CP2];
__device__ int    g_start[NUM_GRAPHS + 1];
__device__ float  g_readout[NUM_GRAPHS * NUM_CLASSES];

// ---------------- PTX helpers (portable, no 'a' features) ----------------
__device__ __forceinline__ void cp16(uint32_t dst_smem, const void* src) {
    asm volatile("cp.async.cg.shared.global [%0], [%1], 16;" :: "r"(dst_smem), "l"(src));
}
#define CP_COMMIT() asm volatile("cp.async.commit_group;" ::: "memory")
#define CP_WAIT0()  asm volatile("cp.async.wait_group 0;" ::: "memory")

__device__ __forceinline__ uint32_t pack2(float lo, float hi) {
    uint32_t r;
    asm("cvt.rn.f16x2.f32 %0, %1, %2;" : "=r"(r) : "f"(hi), "f"(lo));  // a->hi, b->lo
    return r;
}
__device__ __forceinline__ void mma16(float c[4], const uint32_t a[4], uint32_t b0, uint32_t b1) {
    asm volatile(
        "mma.sync.aligned.m16n8k16.row.col.f32.f16.f16.f32 "
        "{%0,%1,%2,%3}, {%4,%5,%6,%7}, {%8,%9}, {%0,%1,%2,%3};"
        : "+f"(c[0]), "+f"(c[1]), "+f"(c[2]), "+f"(c[3])
        : "r"(a[0]), "r"(a[1]), "r"(a[2]), "r"(a[3]), "r"(b0), "r"(b1));
}
__device__ __forceinline__ void ldsm4(uint32_t r[4], uint32_t addr) {
    asm volatile("ldmatrix.sync.aligned.m8n8.x4.shared.b16 {%0,%1,%2,%3}, [%4];"
                 : "=r"(r[0]), "=r"(r[1]), "=r"(r[2]), "=r"(r[3]) : "r"(addr));
}

// ---------------- prep: transpose + pad (112) + fp16-convert weights ----------------
__global__ void prep_kernel(const float* __restrict__ Wg, const float* __restrict__ bg,
                            const float* __restrict__ Wt, const float* __restrict__ bt) {
    int i = blockIdx.x * blockDim.x + threadIdx.x;
    if (i < CP2 * 2 * HIDDEN) {
        int n = i >> 9, k = i & 511;
        g_Wg_h[i] = __float2half_rn((n < NUM_CLASSES) ? Wg[k * NUM_CLASSES + n] : 0.f);
    }
    if (i < CP2 * HIDDEN) {
        int n = i >> 8, k = i & 255;
        g_Wt_h[i] = __float2half_rn((n < NUM_CLASSES) ? Wt[k * NUM_CLASSES + n] : 0.f);
    }
    if (i < CP2) {
        g_bg_pad[i] = (i < NUM_CLASSES) ? bg[i] : 0.f;
        g_bt_pad[i] = (i < NUM_CLASSES) ? bt[i] : 0.f;
    }
}

// ---------------- graph segment starts (sorted ids) ----------------
__global__ void starts_kernel(const int* __restrict__ gl, int n) {
    int g = blockIdx.x * blockDim.x + threadIdx.x;
    if (g > NUM_GRAPHS) return;
    int lo = 0, hi = n;
    while (lo < hi) {
        int mid = (lo + hi) >> 1;
        if (gl[mid] < g) lo = mid + 1; else hi = mid;
    }
    g_start[g] = lo;
}

// ---------------- main fused kernel: one block (512 thr) per graph ----------------
// 8 K64 stages per 128-node tile: s<4 pass1 (xi, gate), s>=4 pass2 (xf, gate+trans)
__global__ __launch_bounds__(512, 1) void fused_node_tc(
        const float* __restrict__ xi, const float* __restrict__ xf) {
    extern __shared__ __half sm[];

    const int tid  = threadIdx.x;
    const int lane = tid & 31;
    const int wid  = tid >> 5;
    const int gid  = lane >> 2;     // 0..7
    const int tig  = lane & 3;      // 0..3
    const int wc   = wid & 7;       // column warp group (0..6 compute, 7 idle)
    const int rh   = wid >> 3;      // row half (0/1)
    const int nbw  = (wc < 7 ? wc : 0) * 16;
    const int rh64 = rh * 64;
    const bool cw  = (wc < 7);

    const uint32_t smu = (uint32_t)__cvta_generic_to_shared(sm);

    // ---- load ALL weights into smem once (cp.async fp16) ----
    #pragma unroll
    for (int i = 0; i < 14; i++) {
        int idx = i * 512 + tid;
        int n = idx >> 6, kq = idx & 63;
        cp16(smu + (uint32_t)(WG_OFF + n * WG_ST + kq * 8) * 2u, g_Wg_h + n * 512 + kq * 8);
    }
    #pragma unroll
    for (int i = 0; i < 7; i++) {
        int idx = i * 512 + tid;
        int n = idx >> 5, kq = idx & 31;
        cp16(smu + (uint32_t)(WT_OFF + n * WT_ST + kq * 8) * 2u, g_Wt_h + n * 256 + kq * 8);
    }
    CP_COMMIT();

    const int g = blockIdx.x;
    const int s0 = g_start[g], e = g_start[g + 1];

    // ldmatrix base addresses (bytes)
    const uint32_t aBase = smu + 2u * (uint32_t)(A_OFF + (rh64 + (lane & 15)) * AS_ST
                                                 + ((lane >> 4) & 1) * 8);
    const int wrow = nbw + (lane & 7) + ((lane >> 4) & 1) * 8;
    const uint32_t wgBase = smu + 2u * (uint32_t)(WG_OFF + wrow * WG_ST + ((lane >> 3) & 1) * 8);
    const uint32_t wtBase = smu + 2u * (uint32_t)(WT_OFF + wrow * WT_ST + ((lane >> 3) & 1) * 8);

    // per-thread biases for owned columns
    float bgE[2], bgO[2], btE[2], btO[2];
    #pragma unroll
    for (int nt = 0; nt < 2; nt++) {
        int cE = nbw + nt * 8 + 2 * tig;
        bgE[nt] = g_bg_pad[cE]; bgO[nt] = g_bg_pad[cE + 1];
        btE[nt] = g_bt_pad[cE]; btO[nt] = g_bt_pad[cE + 1];
    }
    float sumE[2] = {0.f, 0.f}, sumO[2] = {0.f, 0.f};

    const int ar  = tid >> 2;        // A staging: row 0..127
    const int acq = (tid & 3) * 16;  // col chunk (16 floats)

    CP_WAIT0();
    __syncthreads();                 // W resident for all

    for (int t0 = s0; t0 < e; t0 += 128) {
        float accG[4][2][4], accT[4][2][4];
        #pragma unroll
        for (int rg = 0; rg < 4; rg++)
            #pragma unroll
            for (int nt = 0; nt < 2; nt++)
                #pragma unroll
                for (int j = 0; j < 4; j++) { accG[rg][nt][j] = 0.f; accT[rg][nt][j] = 0.f; }

        // prologue: LDG A stage 0 (src=xi, kb=0)
        float4 v0, v1, v2, v3;
        {
            int row = t0 + ar; if (row > N_NODES - 1) row = N_NODES - 1;
            const float* p = xi + (size_t)row * HIDDEN + acq;
            v0 = *(const float4*)p;       v1 = *(const float4*)(p + 4);
            v2 = *(const float4*)(p + 8); v3 = *(const float4*)(p + 12);
        }

        for (int s = 0; s < 8; s++) {
            // STS stage s (regs -> fp16 smem, double-buffered)
            {
                uint32_t h0 = pack2(v0.x, v0.y), h1 = pack2(v0.z, v0.w);
                uint32_t h2 = pack2(v1.x, v1.y), h3 = pack2(v1.z, v1.w);
                uint32_t h4 = pack2(v2.x, v2.y), h5 = pack2(v2.z, v2.w);
                uint32_t h6 = pack2(v3.x, v3.y), h7 = pack2(v3.z, v3.w);
                uint32_t d = smu + (uint32_t)(A_OFF + (s & 1) * A_BUF + ar * AS_ST + acq) * 2u;
                asm volatile("st.shared.v4.b32 [%0], {%1,%2,%3,%4};"
                             :: "r"(d), "r"(h0), "r"(h1), "r"(h2), "r"(h3));
                asm volatile("st.shared.v4.b32 [%0], {%1,%2,%3,%4};"
                             :: "r"(d + 16u), "r"(h4), "r"(h5), "r"(h6), "r"(h7));
            }
            // LDG A stage s+1
            if (s + 1 < 8) {
                int s1 = s + 1;
                const float* src = (s1 < 4) ? xi : xf;
                int kb = (s1 & 3) * 64;
                int row = t0 + ar; if (row > N_NODES - 1) row = N_NODES - 1;
                const float* p = src + (size_t)row * HIDDEN + kb + acq;
                v0 = *(const float4*)p;       v1 = *(const float4*)(p + 4);
                v2 = *(const float4*)(p + 8); v3 = *(const float4*)(p + 12);
            }
            __syncthreads();

            // ---- compute stage s (ldmatrix + mma), col-warps 0..6 only ----
            if (cw) {
                const uint32_t aS = aBase + (uint32_t)((s & 1) * A_BUF) * 2u;
                const int kg = s * 64;
                const int kt = (s - 4) * 64;
                const bool p2 = (s >= 4);
                #pragma unroll
                for (int kk = 0; kk < 64; kk += 16) {
                    uint32_t a[4][4];
                    #pragma unroll
                    for (int rg = 0; rg < 4; rg++)
                        ldsm4(a[rg], aS + (uint32_t)(rg * 16 * AS_ST + kk) * 2u);
                    uint32_t bgf[4];
                    ldsm4(bgf, wgBase + (uint32_t)(kg + kk) * 2u);
                    #pragma unroll
                    for (int rg = 0; rg < 4; rg++) {
                        mma16(accG[rg][0], a[rg], bgf[0], bgf[1]);
                        mma16(accG[rg][1], a[rg], bgf[2], bgf[3]);
                    }
                    if (p2) {
                        uint32_t btf[4];
                        ldsm4(btf, wtBase + (uint32_t)(kt + kk) * 2u);
                        #pragma unroll
                        for (int rg = 0; rg < 4; rg++) {
                            mma16(accT[rg][0], a[rg], btf[0], btf[1]);
                            mma16(accT[rg][1], a[rg], btf[2], btf[3]);
                        }
                    }
                }
            }
            __syncthreads();
        }

        // epilogue: sigmoid(gate)*trans, mask tail rows, fold into per-graph sums
        int cnt = e - t0; if (cnt > 128) cnt = 128;
        if (cw) {
            #pragma unroll
            for (int nt = 0; nt < 2; nt++) {
                #pragma unroll
                for (int rg = 0; rg < 4; rg++) {
                    int r0 = rh64 + rg * 16 + gid;
                    int r1 = r0 + 8;
                    if (r0 < cnt) {
                        float g0 = accG[rg][nt][0] + bgE[nt];
                        float g1 = accG[rg][nt][1] + bgO[nt];
                        float t0v = accT[rg][nt][0] + btE[nt];
                        float t1v = accT[rg][nt][1] + btO[nt];
                        sumE[nt] += t0v * __fdividef(1.f, 1.f + __expf(-g0));
                        sumO[nt] += t1v * __fdividef(1.f, 1.f + __expf(-g1));
                    }
                    if (r1 < cnt) {
                        float g2 = accG[rg][nt][2] + bgE[nt];
                        float g3 = accG[rg][nt][3] + bgO[nt];
                        float t2v = accT[rg][nt][2] + btE[nt];
                        float t3v = accT[rg][nt][3] + btO[nt];
                        sumE[nt] += t2v * __fdividef(1.f, 1.f + __expf(-g2));
                        sumO[nt] += t3v * __fdividef(1.f, 1.f + __expf(-g3));
                    }
                }
            }
        }
    }

    // ---- final per-graph reduction (sAcc reuses A-buffer smem) ----
    __syncthreads();
    float* sAcc = (float*)(sm + A_OFF);
    if (tid < CP2) sAcc[tid] = 0.f;
    __syncthreads();
    if (cw) {
        #pragma unroll
        for (int nt = 0; nt < 2; nt++) {
            float vE = sumE[nt], vO = sumO[nt];
            #pragma unroll
            for (int m = 4; m <= 16; m <<= 1) {
                vE += __shfl_xor_sync(0xffffffffu, vE, m);
                vO += __shfl_xor_sync(0xffffffffu, vO, m);
            }
            if (gid == 0) {
                int cE = nbw + nt * 8 + 2 * tig;
                atomicAdd(&sAcc[cE], vE);
                atomicAdd(&sAcc[cE + 1], vO);
            }
        }
    }
    __syncthreads();
    if (tid < NUM_CLASSES) g_readout[g * NUM_CLASSES + tid] = sAcc[tid];
}

// ---------------- BN + MLP: one block (128 thr) per graph, weights via L2 ----------------
__global__ void mlp_kernel(const float* __restrict__ aux,
                           const float* __restrict__ bn_gamma, const float* __restrict__ bn_beta,
                           const float* __restrict__ bn_mean,  const float* __restrict__ bn_var,
                           const float* __restrict__ W1, const float* __restrict__ b1,
                           const float* __restrict__ W2, const float* __restrict__ b2,
                           float* __restrict__ out) {
    __shared__ float sn[D_IN];
    __shared__ float sh[GRAPH_X];
    int g = blockIdx.x, tid = threadIdx.x;
    if (tid < D_IN) {
        float v = (tid < NUM_CLASSES) ? g_readout[g * NUM_CLASSES + tid]
                                      : aux[g * AUX_DIM + (tid - NUM_CLASSES)];
        sn[tid] = (v - bn_mean[tid]) * rsqrtf(bn_var[tid] + 1e-5f) * bn_gamma[tid] + bn_beta[tid];
    }
    __syncthreads();
    {
        float acc = b1[tid];
        #pragma unroll 2
        for (int d = 0; d < D_IN; d++) acc = fmaf(sn[d], W1[d * GRAPH_X + tid], acc);
        sh[tid] = fmaxf(acc, 0.f);
    }
    __syncthreads();
    if (tid < NUM_CLASSES) {
        float acc = b2[tid];
        #pragma unroll 4
        for (int j = 0; j < GRAPH_X; j++) acc = fmaf(sh[j], W2[j * NUM_CLASSES + tid], acc);
        out[g * NUM_CLASSES + tid] = acc;
    }
}

// ---------------- launch ----------------
extern "C" void kernel_launch(void* const* d_in, const int* in_sizes, int n_in,
                              void* d_out, int out_size) {
    int o = (n_in > 4 && in_sizes[4] == 1) ? 1 : 0;
    const float* xi  = (const float*)d_in[0];
    const float* xf  = (const float*)d_in[1];
    const float* aux = (const float*)d_in[2];
    const int*   gl  = (const int*)  d_in[3];
    const float* Wg  = (const float*)d_in[4 + o];
    const float* bg  = (const float*)d_in[5 + o];
    const float* Wt  = (const float*)d_in[6 + o];
    const float* bt  = (const float*)d_in[7 + o];
    const float* bn_gamma = (const float*)d_in[8 + o];
    const float* bn_beta  = (const float*)d_in[9 + o];
    const float* bn_mean  = (const float*)d_in[10 + o];
    const float* bn_var   = (const float*)d_in[11 + o];
    const float* W1 = (const float*)d_in[12 + o];
    const float* b1 = (const float*)d_in[13 + o];
    const float* W2 = (const float*)d_in[14 + o];
    const float* b2 = (const float*)d_in[15 + o];
    float* out = (float*)d_out;

    cudaFuncSetAttribute(fused_node_tc, cudaFuncAttributeMaxDynamicSharedMemorySize, DYN_BYTES);

    prep_kernel<<<(CP2 * 2 * HIDDEN + 255) / 256, 256>>>(Wg, bg, Wt, bt);
    starts_kernel<<<(NUM_GRAPHS + 1 + 255) / 256, 256>>>(gl, N_NODES);
    fused_node_tc<<<NUM_GRAPHS, 512, DYN_BYTES>>>(xi, xf);
    mlp_kernel<<<NUM_GRAPHS, GRAPH_X>>>(aux, bn_gamma, bn_beta, bn_mean, bn_var,
                                        W1, b1, W2, b2, out);
}

// round 14
// speedup vs baseline: 1.1567x; 1.1567x over previous
#include <cuda_runtime.h>
#include <cuda_fp16.h>
#include <cstdint>
#include <math.h>

#define N_NODES     500000
#define HIDDEN      256
#define NUM_CLASSES 104
#define AUX_DIM     2
#define NUM_GRAPHS  2048
#define D_IN        (NUM_CLASSES + AUX_DIM)   // 106
#define GRAPH_X     128
#define CP          128                        // padded class dim

// smem layout (units: halves)
#define WG_ST   520                            // Wg row stride (k), pad 8
#define WT_ST   264                            // Wt row stride
#define AS_ST   40                             // A row stride (32 + pad 8)
#define WG_OFF  0                              // 128*520 = 66560
#define WT_OFF  66560                          // 128*264 = 33792
#define A_OFF   100352
#define A_BUF   (128 * AS_ST)                  // 5120
#define DYN_BYTES ((A_OFF + 2 * A_BUF) * 2)    // 221184 bytes

// ---------------- device scratch ----------------
__device__ __half g_Wg_h[CP * 2 * HIDDEN];     // [128 n][512 k] fp16
__device__ __half g_Wt_h[CP * HIDDEN];         // [128 n][256 k] fp16
__device__ float  g_bg_pad[CP];
__device__ float  g_bt_pad[CP];
__device__ int    g_start[NUM_GRAPHS + 1];
__device__ float  g_readout[NUM_GRAPHS * NUM_CLASSES];

// ---------------- PTX helpers (portable, no 'a' features) ----------------
__device__ __forceinline__ void cp16(uint32_t dst_smem, const void* src) {
    asm volatile("cp.async.cg.shared.global [%0], [%1], 16;" :: "r"(dst_smem), "l"(src));
}
#define CP_COMMIT() asm volatile("cp.async.commit_group;" ::: "memory")
#define CP_WAIT0()  asm volatile("cp.async.wait_group 0;" ::: "memory")

__device__ __forceinline__ uint32_t pack2(float lo, float hi) {
    uint32_t r;
    asm("cvt.rn.f16x2.f32 %0, %1, %2;" : "=r"(r) : "f"(hi), "f"(lo));  // a->hi, b->lo
    return r;
}
__device__ __forceinline__ void mma16(float c[4], const uint32_t a[4], uint32_t b0, uint32_t b1) {
    asm volatile(
        "mma.sync.aligned.m16n8k16.row.col.f32.f16.f16.f32 "
        "{%0,%1,%2,%3}, {%4,%5,%6,%7}, {%8,%9}, {%0,%1,%2,%3};"
        : "+f"(c[0]), "+f"(c[1]), "+f"(c[2]), "+f"(c[3])
        : "r"(a[0]), "r"(a[1]), "r"(a[2]), "r"(a[3]), "r"(b0), "r"(b1));
}
__device__ __forceinline__ void ldsm4(uint32_t r[4], uint32_t addr) {
    asm volatile("ldmatrix.sync.aligned.m8n8.x4.shared.b16 {%0,%1,%2,%3}, [%4];"
                 : "=r"(r[0]), "=r"(r[1]), "=r"(r[2]), "=r"(r[3]) : "r"(addr));
}

// ---------------- prep: transpose + pad + fp16-convert weights ----------------
__global__ void prep_kernel(const float* __restrict__ Wg, const float* __restrict__ bg,
                            const float* __restrict__ Wt, const float* __restrict__ bt) {
    int i = blockIdx.x * blockDim.x + threadIdx.x;
    if (i < CP * 2 * HIDDEN) {
        int n = i >> 9, k = i & 511;
        g_Wg_h[i] = __float2half_rn((n < NUM_CLASSES) ? Wg[k * NUM_CLASSES + n] : 0.f);
    }
    if (i < CP * HIDDEN) {
        int n = i >> 8, k = i & 255;
        g_Wt_h[i] = __float2half_rn((n < NUM_CLASSES) ? Wt[k * NUM_CLASSES + n] : 0.f);
    }
    if (i < CP) {
        g_bg_pad[i] = (i < NUM_CLASSES) ? bg[i] : 0.f;
        g_bt_pad[i] = (i < NUM_CLASSES) ? bt[i] : 0.f;
    }
}

// ---------------- graph segment starts (sorted ids) ----------------
__global__ void starts_kernel(const int* __restrict__ gl, int n) {
    int g = blockIdx.x * blockDim.x + threadIdx.x;
    if (g > NUM_GRAPHS) return;
    int lo = 0, hi = n;
    while (lo < hi) {
        int mid = (lo + hi) >> 1;
        if (gl[mid] < g) lo = mid + 1; else hi = mid;
    }
    g_start[g] = lo;
}

// ---------------- main fused kernel: PERSISTENT blocks (512 thr) ----------------
// Block b handles graphs b, b+gridDim.x, ... with weights loaded into smem ONCE.
__global__ __launch_bounds__(512, 1) void fused_node_tc(
        const float* __restrict__ xi, const float* __restrict__ xf) {
    extern __shared__ __half sm[];

    const int tid  = threadIdx.x;
    const int lane = tid & 31;
    const int wid  = tid >> 5;
    const int gid  = lane >> 2;     // 0..7
    const int tig  = lane & 3;      // 0..3
    const int wc   = wid & 7;       // column warp group
    const int rh   = wid >> 3;      // row half (0/1)
    const int nb   = wc * 16;
    const int rh64 = rh * 64;

    const uint32_t smu = (uint32_t)__cvta_generic_to_shared(sm);

    // ---- load ALL weights into smem once per block (cp.async fp16) ----
    #pragma unroll
    for (int i = 0; i < 16; i++) {
        int idx = i * 512 + tid;
        int n = idx >> 6, kq = idx & 63;
        cp16(smu + (uint32_t)(WG_OFF + n * WG_ST + kq * 8) * 2u, g_Wg_h + n * 512 + kq * 8);
    }
    #pragma unroll
    for (int i = 0; i < 8; i++) {
        int idx = i * 512 + tid;
        int n = idx >> 5, kq = idx & 31;
        cp16(smu + (uint32_t)(WT_OFF + n * WT_ST + kq * 8) * 2u, g_Wt_h + n * 256 + kq * 8);
    }
    CP_COMMIT();

    // ldmatrix base addresses (bytes)
    const uint32_t aBase = smu + 2u * (uint32_t)(A_OFF + (rh64 + (lane & 15)) * AS_ST
                                                 + ((lane >> 4) & 1) * 8);
    const int wrow = nb + (lane & 7) + ((lane >> 4) & 1) * 8;
    const uint32_t wgBase = smu + 2u * (uint32_t)(WG_OFF + wrow * WG_ST + ((lane >> 3) & 1) * 8);
    const uint32_t wtBase = smu + 2u * (uint32_t)(WT_OFF + wrow * WT_ST + ((lane >> 3) & 1) * 8);

    // per-thread biases for owned columns (graph-independent)
    float bgE[2], bgO[2], btE[2], btO[2];
    #pragma unroll
    for (int nt = 0; nt < 2; nt++) {
        int cE = nb + nt * 8 + 2 * tig;
        bgE[nt] = g_bg_pad[cE]; bgO[nt] = g_bg_pad[cE + 1];
        btE[nt] = g_bt_pad[cE]; btO[nt] = g_bt_pad[cE + 1];
    }

    const int ar  = tid >> 2;        // A staging: row 0..127
    const int acq = (tid & 3) * 8;   // col chunk (8 floats)

    CP_WAIT0();
    __syncthreads();                 // W resident for all

    for (int g = blockIdx.x; g < NUM_GRAPHS; g += gridDim.x) {
        const int s0 = g_start[g], e = g_start[g + 1];
        float sumE[2] = {0.f, 0.f}, sumO[2] = {0.f, 0.f};

        for (int t0 = s0; t0 < e; t0 += 128) {
            float accG[4][2][4], accT[4][2][4];
            #pragma unroll
            for (int rg = 0; rg < 4; rg++)
                #pragma unroll
                for (int nt = 0; nt < 2; nt++)
                    #pragma unroll
                    for (int j = 0; j < 4; j++) { accG[rg][nt][j] = 0.f; accT[rg][nt][j] = 0.f; }

            // prologue: LDG A stage 0 (src=xi, kb=0)
            float4 v0, v1;
            {
                int row = t0 + ar; if (row > N_NODES - 1) row = N_NODES - 1;
                const float* p = xi + (size_t)row * HIDDEN + acq;
                v0 = *(const float4*)p;
                v1 = *(const float4*)(p + 4);
            }

            for (int s = 0; s < 16; s++) {
                // STS stage s (regs -> fp16 smem, double-buffered)
                {
                    uint32_t h0 = pack2(v0.x, v0.y), h1 = pack2(v0.z, v0.w);
                    uint32_t h2 = pack2(v1.x, v1.y), h3 = pack2(v1.z, v1.w);
                    uint32_t d = smu + (uint32_t)(A_OFF + (s & 1) * A_BUF + ar * AS_ST + acq) * 2u;
                    asm volatile("st.shared.v4.b32 [%0], {%1,%2,%3,%4};"
                                 :: "r"(d), "r"(h0), "r"(h1), "r"(h2), "r"(h3));
                }
                // LDG A stage s+1
                if (s + 1 < 16) {
                    int s1 = s + 1;
                    const float* src = (s1 < 8) ? xi : xf;
                    int kb = (s1 & 7) * 32;
                    int row = t0 + ar; if (row > N_NODES - 1) row = N_NODES - 1;
                    const float* p = src + (size_t)row * HIDDEN + kb + acq;
                    v0 = *(const float4*)p;
                    v1 = *(const float4*)(p + 4);
                }
                __syncthreads();

                // ---- compute stage s (ldmatrix + mma) ----
                const uint32_t aS = aBase + (uint32_t)((s & 1) * A_BUF) * 2u;
                const int kg = s * 32;
                const int kt = (s - 8) * 32;
                const bool p2 = (s >= 8);
                #pragma unroll
                for (int kk = 0; kk < 32; kk += 16) {
                    uint32_t a[4][4];
                    #pragma unroll
                    for (int rg = 0; rg < 4; rg++)
                        ldsm4(a[rg], aS + (uint32_t)(rg * 16 * AS_ST + kk) * 2u);
                    uint32_t bgf[4];
                    ldsm4(bgf, wgBase + (uint32_t)(kg + kk) * 2u);
                    #pragma unroll
                    for (int rg = 0; rg < 4; rg++) {
                        mma16(accG[rg][0], a[rg], bgf[0], bgf[1]);
                        mma16(accG[rg][1], a[rg], bgf[2], bgf[3]);
                    }
                    if (p2) {
                        uint32_t btf[4];
                        ldsm4(btf, wtBase + (uint32_t)(kt + kk) * 2u);
                        #pragma unroll
                        for (int rg = 0; rg < 4; rg++) {
                            mma16(accT[rg][0], a[rg], btf[0], btf[1]);
                            mma16(accT[rg][1], a[rg], btf[2], btf[3]);
                        }
                    }
                }
            }

            // epilogue: sigmoid(gate)*trans, mask tail rows, fold into per-graph sums
            int cnt = e - t0; if (cnt > 128) cnt = 128;
            #pragma unroll
            for (int nt = 0; nt < 2; nt++) {
                #pragma unroll
                for (int rg = 0; rg < 4; rg++) {
                    int r0 = rh64 + rg * 16 + gid;
                    int r1 = r0 + 8;
                    if (r0 < cnt) {
                        float g0 = accG[rg][nt][0] + bgE[nt];
                        float g1 = accG[rg][nt][1] + bgO[nt];
                        float t0v = accT[rg][nt][0] + btE[nt];
                        float t1v = accT[rg][nt][1] + btO[nt];
                        sumE[nt] += t0v * __fdividef(1.f, 1.f + __expf(-g0));
                        sumO[nt] += t1v * __fdividef(1.f, 1.f + __expf(-g1));
                    }
                    if (r1 < cnt) {
                        float g2 = accG[rg][nt][2] + bgE[nt];
                        float g3 = accG[rg][nt][3] + bgO[nt];
                        float t2v = accT[rg][nt][2] + btE[nt];
                        float t3v = accT[rg][nt][3] + btO[nt];
                        sumE[nt] += t2v * __fdividef(1.f, 1.f + __expf(-g2));
                        sumO[nt] += t3v * __fdividef(1.f, 1.f + __expf(-g3));
                    }
                }
            }
        }

        // ---- per-graph reduction (sAcc aliases A-buffer smem; mainloop done) ----
        __syncthreads();
        float* sAcc = (float*)(sm + A_OFF);
        if (tid < CP) sAcc[tid] = 0.f;
        __syncthreads();
        #pragma unroll
        for (int nt = 0; nt < 2; nt++) {
            float vE = sumE[nt], vO = sumO[nt];
            #pragma unroll
            for (int m = 4; m <= 16; m <<= 1) {
                vE += __shfl_xor_sync(0xffffffffu, vE, m);
                vO += __shfl_xor_sync(0xffffffffu, vO, m);
            }
            if (gid == 0) {
                int cE = nb + nt * 8 + 2 * tig;
                atomicAdd(&sAcc[cE], vE);
                atomicAdd(&sAcc[cE + 1], vO);
            }
        }
        __syncthreads();
        if (tid < NUM_CLASSES) g_readout[g * NUM_CLASSES + tid] = sAcc[tid];
        __syncthreads();   // protect sAcc region before next graph's A staging
    }
}

// ---------------- BN + MLP: one block (128 thr) per graph, weights via L2 ----------------
__global__ void mlp_kernel(const float* __restrict__ aux,
                           const float* __restrict__ bn_gamma, const float* __restrict__ bn_beta,
                           const float* __restrict__ bn_mean,  const float* __restrict__ bn_var,
                           const float* __restrict__ W1, const float* __restrict__ b1,
                           const float* __restrict__ W2, const float* __restrict__ b2,
                           float* __restrict__ out) {
    __shared__ float sn[D_IN];
    __shared__ float sh[GRAPH_X];
    int g = blockIdx.x, tid = threadIdx.x;
    if (tid < D_IN) {
        float v = (tid < NUM_CLASSES) ? g_readout[g * NUM_CLASSES + tid]
                                      : aux[g * AUX_DIM + (tid - NUM_CLASSES)];
        sn[tid] = (v - bn_mean[tid]) * rsqrtf(bn_var[tid] + 1e-5f) * bn_gamma[tid] + bn_beta[tid];
    }
    __syncthreads();
    {
        float acc = b1[tid];
        #pragma unroll 2
        for (int d = 0; d < D_IN; d++) acc = fmaf(sn[d], W1[d * GRAPH_X + tid], acc);
        sh[tid] = fmaxf(acc, 0.f);
    }
    __syncthreads();
    if (tid < NUM_CLASSES) {
        float acc = b2[tid];
        #pragma unroll 4
        for (int j = 0; j < GRAPH_X; j++) acc = fmaf(sh[j], W2[j * NUM_CLASSES + tid], acc);
        out[g * NUM_CLASSES + tid] = acc;
    }
}

// ---------------- launch ----------------
extern "C" void kernel_launch(void* const* d_in, const int* in_sizes, int n_in,
                              void* d_out, int out_size) {
    int o = (n_in > 4 && in_sizes[4] == 1) ? 1 : 0;
    const float* xi  = (const float*)d_in[0];
    const float* xf  = (const float*)d_in[1];
    const float* aux = (const float*)d_in[2];
    const int*   gl  = (const int*)  d_in[3];
    const float* Wg  = (const float*)d_in[4 + o];
    const float* bg  = (const float*)d_in[5 + o];
    const float* Wt  = (const float*)d_in[6 + o];
    const float* bt  = (const float*)d_in[7 + o];
    const float* bn_gamma = (const float*)d_in[8 + o];
    const float* bn_beta  = (const float*)d_in[9 + o];
    const float* bn_mean  = (const float*)d_in[10 + o];
    const float* bn_var   = (const float*)d_in[11 + o];
    const float* W1 = (const float*)d_in[12 + o];
    const float* b1 = (const float*)d_in[13 + o];
    const float* W2 = (const float*)d_in[14 + o];
    const float* b2 = (const float*)d_in[15 + o];
    float* out = (float*)d_out;

    cudaFuncSetAttribute(fused_node_tc, cudaFuncAttributeMaxDynamicSharedMemorySize, DYN_BYTES);

    int dev = 0, nsm = 148;
    cudaGetDevice(&dev);
    cudaDeviceGetAttribute(&nsm, cudaDevAttrMultiProcessorCount, dev);

    prep_kernel<<<(CP * 2 * HIDDEN + 255) / 256, 256>>>(Wg, bg, Wt, bt);
    starts_kernel<<<(NUM_GRAPHS + 1 + 255) / 256, 256>>>(gl, N_NODES);
    fused_node_tc<<<nsm, 512, DYN_BYTES>>>(xi, xf);
    mlp_kernel<<<NUM_GRAPHS, GRAPH_X>>>(aux, bn_gamma, bn_beta, bn_mean, bn_var,
                                        W1, b1, W2, b2, out);
}

// round 15
// speedup vs baseline: 1.1910x; 1.0297x over previous
#include <cuda_runtime.h>
#include <cuda_fp16.h>
#include <cstdint>
#include <math.h>

#define N_NODES     500000
#define HIDDEN      256
#define NUM_CLASSES 104
#define AUX_DIM     2
#define NUM_GRAPHS  2048
#define D_IN        (NUM_CLASSES + AUX_DIM)   // 106
#define GRAPH_X     128
#define CP          128                        // padded class dim

// smem layout (units: halves)
#define WG_ST   520
#define WT_ST   264
#define AS_ST   40
#define WG_OFF  0
#define WT_OFF  66560
#define A_OFF   100352
#define A_BUF   (128 * AS_ST)
#define DYN_BYTES ((A_OFF + 2 * A_BUF) * 2)    // 221184 bytes

// ---------------- device scratch ----------------
__device__ __half g_Wg_h[CP * 2 * HIDDEN];
__device__ __half g_Wt_h[CP * HIDDEN];
__device__ float  g_bg_pad[CP];
__device__ float  g_bt_pad[CP];
__device__ int    g_start[NUM_GRAPHS + 1];
__device__ float  g_readout[NUM_GRAPHS * NUM_CLASSES];

// ---------------- PTX helpers (portable, no 'a' features) ----------------
__device__ __forceinline__ void cp16(uint32_t dst_smem, const void* src) {
    asm volatile("cp.async.cg.shared.global [%0], [%1], 16;" :: "r"(dst_smem), "l"(src));
}
#define CP_COMMIT() asm volatile("cp.async.commit_group;" ::: "memory")
#define CP_WAIT0()  asm volatile("cp.async.wait_group 0;" ::: "memory")

__device__ __forceinline__ uint32_t pack2(float lo, float hi) {
    uint32_t r;
    asm("cvt.rn.f16x2.f32 %0, %1, %2;" : "=r"(r) : "f"(hi), "f"(lo));
    return r;
}
__device__ __forceinline__ void mma16(float c[4], const uint32_t a[4], uint32_t b0, uint32_t b1) {
    asm volatile(
        "mma.sync.aligned.m16n8k16.row.col.f32.f16.f16.f32 "
        "{%0,%1,%2,%3}, {%4,%5,%6,%7}, {%8,%9}, {%0,%1,%2,%3};"
        : "+f"(c[0]), "+f"(c[1]), "+f"(c[2]), "+f"(c[3])
        : "r"(a[0]), "r"(a[1]), "r"(a[2]), "r"(a[3]), "r"(b0), "r"(b1));
}
__device__ __forceinline__ void ldsm4(uint32_t r[4], uint32_t addr) {
    asm volatile("ldmatrix.sync.aligned.m8n8.x4.shared.b16 {%0,%1,%2,%3}, [%4];"
                 : "=r"(r[0]), "=r"(r[1]), "=r"(r[2]), "=r"(r[3]) : "r"(addr));
}

// ---------------- prep ----------------
__global__ void prep_kernel(const float* __restrict__ Wg, const float* __restrict__ bg,
                            const float* __restrict__ Wt, const float* __restrict__ bt) {
    int i = blockIdx.x * blockDim.x + threadIdx.x;
    if (i < CP * 2 * HIDDEN) {
        int n = i >> 9, k = i & 511;
        g_Wg_h[i] = __float2half_rn((n < NUM_CLASSES) ? Wg[k * NUM_CLASSES + n] : 0.f);
    }
    if (i < CP * HIDDEN) {
        int n = i >> 8, k = i & 255;
        g_Wt_h[i] = __float2half_rn((n < NUM_CLASSES) ? Wt[k * NUM_CLASSES + n] : 0.f);
    }
    if (i < CP) {
        g_bg_pad[i] = (i < NUM_CLASSES) ? bg[i] : 0.f;
        g_bt_pad[i] = (i < NUM_CLASSES) ? bt[i] : 0.f;
    }
}

// ---------------- graph segment starts ----------------
__global__ void starts_kernel(const int* __restrict__ gl, int n) {
    int g = blockIdx.x * blockDim.x + threadIdx.x;
    if (g > NUM_GRAPHS) return;
    int lo = 0, hi = n;
    while (lo < hi) {
        int mid = (lo + hi) >> 1;
        if (gl[mid] < g) lo = mid + 1; else hi = mid;
    }
    g_start[g] = lo;
}

// ---------------- dummy: shifts ncu -s window onto fused_node_tc ----------------
__global__ void align_dummy_kernel() {}

// ---------------- main fused kernel: PERSISTENT blocks (512 thr) ----------------
__global__ __launch_bounds__(512, 1) void fused_node_tc(
        const float* __restrict__ xi, const float* __restrict__ xf) {
    extern __shared__ __half sm[];

    const int tid  = threadIdx.x;
    const int lane = tid & 31;
    const int wid  = tid >> 5;
    const int gid  = lane >> 2;
    const int tig  = lane & 3;
    const int wc   = wid & 7;
    const int rh   = wid >> 3;
    const int nb   = wc * 16;
    const int rh64 = rh * 64;

    const uint32_t smu = (uint32_t)__cvta_generic_to_shared(sm);

    // ---- load ALL weights into smem once per block ----
    #pragma unroll
    for (int i = 0; i < 16; i++) {
        int idx = i * 512 + tid;
        int n = idx >> 6, kq = idx & 63;
        cp16(smu + (uint32_t)(WG_OFF + n * WG_ST + kq * 8) * 2u, g_Wg_h + n * 512 + kq * 8);
    }
    #pragma unroll
    for (int i = 0; i < 8; i++) {
        int idx = i * 512 + tid;
        int n = idx >> 5, kq = idx & 31;
        cp16(smu + (uint32_t)(WT_OFF + n * WT_ST + kq * 8) * 2u, g_Wt_h + n * 256 + kq * 8);
    }
    CP_COMMIT();

    const uint32_t aBase = smu + 2u * (uint32_t)(A_OFF + (rh64 + (lane & 15)) * AS_ST
                                                 + ((lane >> 4) & 1) * 8);
    const int wrow = nb + (lane & 7) + ((lane >> 4) & 1) * 8;
    const uint32_t wgBase = smu + 2u * (uint32_t)(WG_OFF + wrow * WG_ST + ((lane >> 3) & 1) * 8);
    const uint32_t wtBase = smu + 2u * (uint32_t)(WT_OFF + wrow * WT_ST + ((lane >> 3) & 1) * 8);

    float bgE[2], bgO[2], btE[2], btO[2];
    #pragma unroll
    for (int nt = 0; nt < 2; nt++) {
        int cE = nb + nt * 8 + 2 * tig;
        bgE[nt] = g_bg_pad[cE]; bgO[nt] = g_bg_pad[cE + 1];
        btE[nt] = g_bt_pad[cE]; btO[nt] = g_bt_pad[cE + 1];
    }

    const int ar  = tid >> 2;
    const int acq = (tid & 3) * 8;

    CP_WAIT0();
    __syncthreads();

    for (int g = blockIdx.x; g < NUM_GRAPHS; g += gridDim.x) {
        const int s0 = g_start[g], e = g_start[g + 1];
        float sumE[2] = {0.f, 0.f}, sumO[2] = {0.f, 0.f};

        for (int t0 = s0; t0 < e; t0 += 128) {
            float accG[4][2][4], accT[4][2][4];
            #pragma unroll
            for (int rg = 0; rg < 4; rg++)
                #pragma unroll
                for (int nt = 0; nt < 2; nt++)
                    #pragma unroll
                    for (int j = 0; j < 4; j++) { accG[rg][nt][j] = 0.f; accT[rg][nt][j] = 0.f; }

            float4 v0, v1;
            {
                int row = t0 + ar; if (row > N_NODES - 1) row = N_NODES - 1;
                const float* p = xi + (size_t)row * HIDDEN + acq;
                v0 = *(const float4*)p;
                v1 = *(const float4*)(p + 4);
            }

            for (int s = 0; s < 16; s++) {
                {
                    uint32_t h0 = pack2(v0.x, v0.y), h1 = pack2(v0.z, v0.w);
                    uint32_t h2 = pack2(v1.x, v1.y), h3 = pack2(v1.z, v1.w);
                    uint32_t d = smu + (uint32_t)(A_OFF + (s & 1) * A_BUF + ar * AS_ST + acq) * 2u;
                    asm volatile("st.shared.v4.b32 [%0], {%1,%2,%3,%4};"
                                 :: "r"(d), "r"(h0), "r"(h1), "r"(h2), "r"(h3));
                }
                if (s + 1 < 16) {
                    int s1 = s + 1;
                    const float* src = (s1 < 8) ? xi : xf;
                    int kb = (s1 & 7) * 32;
                    int row = t0 + ar; if (row > N_NODES - 1) row = N_NODES - 1;
                    const float* p = src + (size_t)row * HIDDEN + kb + acq;
                    v0 = *(const float4*)p;
                    v1 = *(const float4*)(p + 4);
                }
                __syncthreads();

                const uint32_t aS = aBase + (uint32_t)((s & 1) * A_BUF) * 2u;
                const int kg = s * 32;
                const int kt = (s - 8) * 32;
                const bool p2 = (s >= 8);
                #pragma unroll
                for (int kk = 0; kk < 32; kk += 16) {
                    uint32_t a[4][4];
                    #pragma unroll
                    for (int rg = 0; rg < 4; rg++)
                        ldsm4(a[rg], aS + (uint32_t)(rg * 16 * AS_ST + kk) * 2u);
                    uint32_t bgf[4];
                    ldsm4(bgf, wgBase + (uint32_t)(kg + kk) * 2u);
                    #pragma unroll
                    for (int rg = 0; rg < 4; rg++) {
                        mma16(accG[rg][0], a[rg], bgf[0], bgf[1]);
                        mma16(accG[rg][1], a[rg], bgf[2], bgf[3]);
                    }
                    if (p2) {
                        uint32_t btf[4];
                        ldsm4(btf, wtBase + (uint32_t)(kt + kk) * 2u);
                        #pragma unroll
                        for (int rg = 0; rg < 4; rg++) {
                            mma16(accT[rg][0], a[rg], btf[0], btf[1]);
                            mma16(accT[rg][1], a[rg], btf[2], btf[3]);
                        }
                    }
                }
            }

            int cnt = e - t0; if (cnt > 128) cnt = 128;
            #pragma unroll
            for (int nt = 0; nt < 2; nt++) {
                #pragma unroll
                for (int rg = 0; rg < 4; rg++) {
                    int r0 = rh64 + rg * 16 + gid;
                    int r1 = r0 + 8;
                    if (r0 < cnt) {
                        float g0 = accG[rg][nt][0] + bgE[nt];
                        float g1 = accG[rg][nt][1] + bgO[nt];
                        float t0v = accT[rg][nt][0] + btE[nt];
                        float t1v = accT[rg][nt][1] + btO[nt];
                        sumE[nt] += t0v * __fdividef(1.f, 1.f + __expf(-g0));
                        sumO[nt] += t1v * __fdividef(1.f, 1.f + __expf(-g1));
                    }
                    if (r1 < cnt) {
                        float g2 = accG[rg][nt][2] + bgE[nt];
                        float g3 = accG[rg][nt][3] + bgO[nt];
                        float t2v = accT[rg][nt][2] + btE[nt];
                        float t3v = accT[rg][nt][3] + btO[nt];
                        sumE[nt] += t2v * __fdividef(1.f, 1.f + __expf(-g2));
                        sumO[nt] += t3v * __fdividef(1.f, 1.f + __expf(-g3));
                    }
                }
            }
        }

        __syncthreads();
        float* sAcc = (float*)(sm + A_OFF);
        if (tid < CP) sAcc[tid] = 0.f;
        __syncthreads();
        #pragma unroll
        for (int nt = 0; nt < 2; nt++) {
            float vE = sumE[nt], vO = sumO[nt];
            #pragma unroll
            for (int m = 4; m <= 16; m <<= 1) {
                vE += __shfl_xor_sync(0xffffffffu, vE, m);
                vO += __shfl_xor_sync(0xffffffffu, vO, m);
            }
            if (gid == 0) {
                int cE = nb + nt * 8 + 2 * tig;
                atomicAdd(&sAcc[cE], vE);
                atomicAdd(&sAcc[cE + 1], vO);
            }
        }
        __syncthreads();
        if (tid < NUM_CLASSES) g_readout[g * NUM_CLASSES + tid] = sAcc[tid];
        __syncthreads();
    }
}

// ---------------- BN + MLP: one block per graph, deeper unroll for MLP ----------------
__global__ void mlp_kernel(const float* __restrict__ aux,
                           const float* __restrict__ bn_gamma, const float* __restrict__ bn_beta,
                           const float* __restrict__ bn_mean,  const float* __restrict__ bn_var,
                           const float* __restrict__ W1, const float* __restrict__ b1,
                           const float* __restrict__ W2, const float* __restrict__ b2,
                           float* __restrict__ out) {
    __shared__ float sn[D_IN];
    __shared__ float sh[GRAPH_X];
    int g = blockIdx.x, tid = threadIdx.x;
    if (tid < D_IN) {
        float v = (tid < NUM_CLASSES) ? g_readout[g * NUM_CLASSES + tid]
                                      : aux[g * AUX_DIM + (tid - NUM_CLASSES)];
        sn[tid] = (v - bn_mean[tid]) * rsqrtf(bn_var[tid] + 1e-5f) * bn_gamma[tid] + bn_beta[tid];
    }
    __syncthreads();
    {
        float acc = b1[tid];
        #pragma unroll 8
        for (int d = 0; d < D_IN; d++) acc = fmaf(sn[d], W1[d * GRAPH_X + tid], acc);
        sh[tid] = fmaxf(acc, 0.f);
    }
    __syncthreads();
    if (tid < NUM_CLASSES) {
        float acc = b2[tid];
        #pragma unroll 8
        for (int j = 0; j < GRAPH_X; j++) acc = fmaf(sh[j], W2[j * NUM_CLASSES + tid], acc);
        out[g * NUM_CLASSES + tid] = acc;
    }
}

// ---------------- launch ----------------
extern "C" void kernel_launch(void* const* d_in, const int* in_sizes, int n_in,
                              void* d_out, int out_size) {
    int o = (n_in > 4 && in_sizes[4] == 1) ? 1 : 0;
    const float* xi  = (const float*)d_in[0];
    const float* xf  = (const float*)d_in[1];
    const float* aux = (const float*)d_in[2];
    const int*   gl  = (const int*)  d_in[3];
    const float* Wg  = (const float*)d_in[4 + o];
    const float* bg  = (const float*)d_in[5 + o];
    const float* Wt  = (const float*)d_in[6 + o];
    const float* bt  = (const float*)d_in[7 + o];
    const float* bn_gamma = (const float*)d_in[8 + o];
    const float* bn_beta  = (const float*)d_in[9 + o];
    const float* bn_mean  = (const float*)d_in[10 + o];
    const float* bn_var   = (const float*)d_in[11 + o];
    const float* W1 = (const float*)d_in[12 + o];
    const float* b1 = (const float*)d_in[13 + o];
    const float* W2 = (const float*)d_in[14 + o];
    const float* b2 = (const float*)d_in[15 + o];
    float* out = (float*)d_out;

    cudaFuncSetAttribute(fused_node_tc, cudaFuncAttributeMaxDynamicSharedMemorySize, DYN_BYTES);

    int dev = 0, nsm = 148;
    cudaGetDevice(&dev);
    cudaDeviceGetAttribute(&nsm, cudaDevAttrMultiProcessorCount, dev);

    prep_kernel<<<(CP * 2 * HIDDEN + 255) / 256, 256>>>(Wg, bg, Wt, bt);
    starts_kernel<<<(NUM_GRAPHS + 1 + 255) / 256, 256>>>(gl, N_NODES);
    align_dummy_kernel<<<1, 32>>>();   // shifts ncu -s window onto fused_node_tc
    fused_node_tc<<<nsm, 512, DYN_BYTES>>>(xi, xf);
    mlp_kernel<<<NUM_GRAPHS, GRAPH_X>>>(aux, bn_gamma, bn_beta, bn_mean, bn_var,
                                        W1, b1, W2, b2, out);
}